// round 2
// baseline (speedup 1.0000x reference)
#include <cuda_runtime.h>
#include <cstdint>

#define BB 16
#define NN 48384
#define KK 512
#define MAXD 100
#define IOU_T 0.45f
#define CONF0 0.25f

#define MASK_OFF (BB * MAXD * 7)          /* 11200 */
#define FEAT_OFF (MASK_OFF + BB * MAXD)   /* 12800 */
#define FEAT_N   (16 * 256 * 48 * 48)     /* 9437184 */

// ---------------- device scratch (static, no allocations) ----------------
__device__ float    g_scores[BB * NN];
__device__ unsigned g_maxbits[BB];   // zero-init; atomicMax is idempotent across graph replays

// ---------------- K1: scores + per-image max ----------------
__global__ void __launch_bounds__(1024) k_scores(const float* __restrict__ pred) {
    const int img = blockIdx.y;
    const int i = blockIdx.x * 1024 + threadIdx.x;
    float s = 0.f;
    if (i < NN) {
        float2 oc = *reinterpret_cast<const float2*>(pred + ((size_t)img * NN + i) * 6 + 4);
        s = __fmul_rn(oc.x, oc.y);
        g_scores[(size_t)img * NN + i] = s;
    }
    __shared__ float red[32];
    #pragma unroll
    for (int o = 16; o; o >>= 1) s = fmaxf(s, __shfl_xor_sync(0xffffffffu, s, o));
    if ((threadIdx.x & 31) == 0) red[threadIdx.x >> 5] = s;
    __syncthreads();
    if (threadIdx.x < 32) {
        float v = red[threadIdx.x];
        #pragma unroll
        for (int o = 16; o; o >>= 1) v = fmaxf(v, __shfl_xor_sync(0xffffffffu, v, o));
        if (threadIdx.x == 0) atomicMax(&g_maxbits[img], __float_as_uint(v));
    }
}

// ---------------- K2: fused select + supmat + NMS + output ----------------
// dynamic smem layout:
//   [0, 65536)        hist[16384] u32  (aliased later as buf[4096] u64 for the sort)
//   [65536, 69632)    upart[1024] u32  (suffix-scan partials)
//   [69632, 86016)    cand arrays: x1,y1,x2,y2,area,obj,conf,valid  (8 x 512 f32)
//   [86016, 118784)   supCol[512][16] u32  (column-major suppression matrix, j<i)
#define SMEM_FUSED 118784

__global__ void __launch_bounds__(1024) k_fused(const float* __restrict__ pred,
                                                float* __restrict__ out) {
    extern __shared__ unsigned char dsm[];
    unsigned*           hist  = reinterpret_cast<unsigned*>(dsm);
    unsigned long long* buf   = reinterpret_cast<unsigned long long*>(dsm);
    unsigned*           upart = reinterpret_cast<unsigned*>(dsm + 65536);
    float* cx1 = reinterpret_cast<float*>(dsm + 69632);
    float* cy1 = cx1 + 512;
    float* cx2 = cy1 + 512;
    float* cy2 = cx2 + 512;
    float* car = cy2 + 512;
    float* cob = car + 512;
    float* ccf = cob + 512;
    float* cvd = ccf + 512;
    unsigned* supc = reinterpret_cast<unsigned*>(dsm + 86016);  // supc[i*16+w]

    __shared__ float    sThr;
    __shared__ unsigned sBstar;
    __shared__ int      sCnt, sTstar, sChanged;
    __shared__ unsigned s_keep[16], s_new[16];
    __shared__ int      s_pfx[16];
    __shared__ int      s_slot[MAXD];

    const int img = blockIdx.x;
    const int tid = threadIdx.x;
    const float* sc = g_scores + (size_t)img * NN;

    // ---- dynamic threshold from precomputed max ----
    if (tid == 0) {
        float mv = __uint_as_float(g_maxbits[img]);
        float t = CONF0;
        for (int it = 0; it < 200 && mv < t; ++it)
            t = fmaxf(__fsub_rn(t, 0.1f), __fdiv_rn(t, 10.0f));
        sThr = t;
        sCnt = 0;
        sTstar = 0;
    }
    for (int i = tid; i < 16384; i += 1024) hist[i] = 0u;
    __syncthreads();
    const float thr = sThr;

    // ---- histogram of masked score bits >> 16 (zeros skipped) ----
    for (int i = tid; i < NN; i += 1024) {
        float s = sc[i];
        float m = (s >= thr) ? s : 0.f;
        unsigned b = __float_as_uint(m) >> 16;
        if (b != 0u) atomicAdd(&hist[b], 1u);
    }
    __syncthreads();

    // ---- suffix scan over 1024 bucket-groups of 16 ----
    unsigned p = 0;
    #pragma unroll
    for (int b = 0; b < 16; ++b) p += hist[tid * 16 + b];
    upart[tid] = p;
    __syncthreads();
    for (int off = 1; off < 1024; off <<= 1) {
        unsigned v = (tid + off < 1024) ? upart[tid + off] : 0u;
        __syncthreads();
        upart[tid] += v;
        __syncthreads();
    }
    if (upart[tid] >= KK && (tid == 1023 || upart[tid + 1] < KK)) sTstar = tid;
    __syncthreads();
    if (tid == 0) {
        unsigned bst;
        if (upart[0] < KK) {
            bst = 1u;   // fewer than 512 positives: collect all positives
        } else {
            int t = sTstar;
            unsigned c = (t < 1023) ? upart[t + 1] : 0u;
            bst = 1u;
            for (int b = t * 16 + 15; b >= t * 16; --b) {
                if (b <= 0) { bst = 1u; break; }
                c += hist[b];
                if (c >= KK) { bst = (unsigned)b; break; }
            }
            if (bst == 0u) bst = 1u;
        }
        sBstar = bst;
    }
    __syncthreads();
    const unsigned bstar = sBstar;

    // ---- gather candidates (hist region now dead -> buf) ----
    for (int i = tid; i < NN; i += 1024) {
        float s = sc[i];
        float m = (s >= thr) ? s : 0.f;
        unsigned bits = __float_as_uint(m);
        if ((bits >> 16) >= bstar) {
            int pz = atomicAdd(&sCnt, 1);
            if (pz < 4096)
                buf[pz] = ((unsigned long long)bits << 32) |
                          (unsigned long long)(0xFFFFFFFFu - (unsigned)i);
        }
    }
    __syncthreads();
    int cnt = sCnt; if (cnt > 4096) cnt = 4096;
    int S = 1024;
    while (S < cnt) S <<= 1;                 // S in {1024,2048,4096}
    for (int i = cnt + tid; i < S; i += 1024) buf[i] = 0ull;
    __syncthreads();

    // ---- bitonic sort, descending; key = scorebits<<32 | ~idx (exact top_k order) ----
    for (int k = 2; k <= S; k <<= 1) {
        for (int j = k >> 1; j > 0; j >>= 1) {
            for (int i = tid; i < S; i += 1024) {
                int l = i ^ j;
                if (l > i) {
                    unsigned long long a = buf[i], b = buf[l];
                    bool up = ((i & k) == 0);
                    if ((a < b) == up) { buf[i] = b; buf[l] = a; }
                }
            }
            __syncthreads();
        }
    }

    // ---- materialize 512 candidates into smem ----
    if (tid < KK) {
        unsigned long long key = buf[tid];
        unsigned bits = (unsigned)(key >> 32);
        unsigned idx  = 0xFFFFFFFFu - (unsigned)(key & 0xFFFFFFFFull);
        float x1 = 0.f, y1 = 0.f, x2 = 0.f, y2 = 0.f, ar = 0.f, ob = 0.f, cf = 0.f, vd = 0.f;
        if (bits != 0u && idx < (unsigned)NN) {
            const float* row = pred + ((size_t)img * NN + idx) * 6;
            float cx = row[0], cy = row[1], w = row[2], h = row[3];
            ob = row[4]; cf = row[5];
            float hw = __fmul_rn(w, 0.5f), hh = __fmul_rn(h, 0.5f);
            x1 = __fsub_rn(cx, hw); y1 = __fsub_rn(cy, hh);
            x2 = __fadd_rn(cx, hw); y2 = __fadd_rn(cy, hh);
            ar = __fmul_rn(fmaxf(__fsub_rn(x2, x1), 0.f),
                           fmaxf(__fsub_rn(y2, y1), 0.f));
            vd = 1.f;
        }
        cx1[tid] = x1; cy1[tid] = y1; cx2[tid] = x2; cy2[tid] = y2;
        car[tid] = ar; cob[tid] = ob; ccf[tid] = cf; cvd[tid] = vd;
    }
    __syncthreads();

    // ---- column-major suppression matrix: supc[i][w] bit l <=> j=32w+l < i and IoU>T ----
    for (int q = tid; q < KK * 16; q += 1024) {
        int i = q >> 4, w = q & 15;
        unsigned bits = 0u;
        int jb = w << 5;
        if (jb < i) {
            float x1 = cx1[i], yy1 = cy1[i], x2 = cx2[i], yy2 = cy2[i], ai = car[i];
            int lmax = i - jb; if (lmax > 32) lmax = 32;
            for (int l = 0; l < lmax; ++l) {
                int j = jb + l;
                float ltx = fmaxf(x1,  cx1[j]);
                float lty = fmaxf(yy1, cy1[j]);
                float rbx = fminf(x2,  cx2[j]);
                float rby = fminf(yy2, cy2[j]);
                float wd = fmaxf(__fsub_rn(rbx, ltx), 0.f);
                float hg = fmaxf(__fsub_rn(rby, lty), 0.f);
                float inter = __fmul_rn(wd, hg);
                float den = __fadd_rn(__fsub_rn(__fadd_rn(ai, car[j]), inter), 1e-9f);
                float iou = __fdiv_rn(inter, den);
                if (iou > IOU_T) bits |= (1u << l);
            }
        }
        supc[q] = bits;
    }

    // ---- keep init = valid ----
    int vbit = (tid < KK) ? (cvd[tid] != 0.f) : 0;
    if (tid < KK) {
        unsigned wb = __ballot_sync(0xffffffffu, vbit);
        if ((tid & 31) == 0) s_keep[tid >> 5] = wb;
    }
    __syncthreads();

    // ---- synchronous fixpoint NMS (unique fixpoint == greedy keep) ----
    for (int r = 0; r < KK; ++r) {
        if (tid == 0) sChanged = 0;
        __syncthreads();
        if (tid < KK) {
            unsigned sup = 0u;
            #pragma unroll
            for (int w = 0; w < 16; ++w) sup |= s_keep[w] & supc[tid * 16 + w];
            int bit = vbit && (sup == 0u);
            unsigned wb = __ballot_sync(0xffffffffu, bit);
            if ((tid & 31) == 0) {
                s_new[tid >> 5] = wb;
                if (wb != s_keep[tid >> 5]) sChanged = 1;
            }
        }
        __syncthreads();
        if (tid < 16) s_keep[tid] = s_new[tid];
        __syncthreads();
        if (!sChanged) break;
    }

    // ---- rank kept boxes, emit top-100 rows + mask ----
    if (tid == 0) {
        int acc = 0;
        for (int w = 0; w < 16; ++w) { s_pfx[w] = acc; acc += __popc(s_keep[w]); }
    }
    if (tid < MAXD) s_slot[tid] = -1;
    __syncthreads();
    if (tid < KK) {
        int w = tid >> 5, b = tid & 31;
        if ((s_keep[w] >> b) & 1u) {
            int rk = s_pfx[w] + __popc(s_keep[w] & ((1u << b) - 1u));
            if (rk < MAXD) s_slot[rk] = tid;
        }
    }
    __syncthreads();
    if (tid < MAXD) {
        int c = s_slot[tid];
        float r0 = 0.f, r1 = 0.f, r2 = 0.f, r3 = 0.f, r4 = 0.f, r5 = 0.f, mk = 0.f;
        if (c >= 0) {
            r0 = cx1[c]; r1 = cy1[c]; r2 = cx2[c]; r3 = cy2[c];
            r4 = cob[c]; r5 = ccf[c]; mk = 1.f;
        }
        float* o = out + (size_t)img * (MAXD * 7) + (size_t)tid * 7;
        o[0] = r0; o[1] = r1; o[2] = r2; o[3] = r3; o[4] = r4; o[5] = r5; o[6] = 0.f;
        out[MASK_OFF + img * MAXD + tid] = mk;
    }
}

// ---------------- launcher ----------------
extern "C" void kernel_launch(void* const* d_in, const int* in_sizes, int n_in,
                              void* d_out, int out_size) {
    const float* pred = (const float*)d_in[0];
    const float* feat = (const float*)d_in[1];
    float* out = (float*)d_out;

    static cudaStream_t s2 = nullptr;
    static cudaEvent_t evA = nullptr, evB = nullptr;
    if (!s2) {
        cudaStreamCreateWithFlags(&s2, cudaStreamNonBlocking);
        cudaEventCreateWithFlags(&evA, cudaEventDisableTiming);
        cudaEventCreateWithFlags(&evB, cudaEventDisableTiming);
        cudaFuncSetAttribute(k_fused, cudaFuncAttributeMaxDynamicSharedMemorySize, SMEM_FUSED);
    }

    // fork: big features copy runs concurrently with the detection pipeline
    cudaEventRecord(evA, 0);
    cudaStreamWaitEvent(s2, evA, 0);
    cudaMemcpyAsync(out + FEAT_OFF, feat, (size_t)FEAT_N * sizeof(float),
                    cudaMemcpyDeviceToDevice, s2);
    cudaEventRecord(evB, s2);

    k_scores<<<dim3(48, BB), 1024>>>(pred);
    k_fused<<<BB, 1024, SMEM_FUSED>>>(pred, out);

    cudaStreamWaitEvent(0, evB, 0);
}

// round 3
// speedup vs baseline: 1.3656x; 1.3656x over previous
#include <cuda_runtime.h>
#include <cstdint>

#define BB 16
#define NN 48384
#define KK 512
#define MAXD 100
#define IOU_T 0.45f
#define CONF0 0.25f
#define HBUCK 16384
#define CAP 4096

#define MASK_OFF (BB * MAXD * 7)          /* 11200 */
#define FEAT_OFF (MASK_OFF + BB * MAXD)   /* 12800 */
#define FEAT_N   (16 * 256 * 48 * 48)     /* 9437184 */

// ---------------- device scratch (static, no allocations) ----------------
__device__ float              g_scores[BB * NN];
__device__ unsigned           g_maxbits[BB];        // atomicMax: idempotent across replays
__device__ unsigned           g_hist[BB * HBUCK];   // zeroed by graph memset node each replay
__device__ int                g_cnt[BB];            // zeroed by graph memset node each replay
__device__ unsigned           g_bstar[BB];
__device__ unsigned long long g_keys[BB * CAP];
__device__ float              g_cand[BB][KK][8];    // x1,y1,x2,y2,area,obj,conf,valid
__device__ unsigned           g_supc[BB][16][KK];   // TRANSPOSED: [word][box] suppressors j<i

__device__ __forceinline__ float calc_thr(float mv) {
    float t = CONF0;
    for (int it = 0; it < 200 && mv < t; ++it)
        t = fmaxf(__fsub_rn(t, 0.1f), __fdiv_rn(t, 10.0f));
    return t;
}

// ---------------- K1: scores + per-image max (grid-wide) ----------------
__global__ void __launch_bounds__(1024) k_scores(const float* __restrict__ pred) {
    const int img = blockIdx.y;
    const int i = blockIdx.x * 1024 + threadIdx.x;
    float s = 0.f;
    if (i < NN) {
        float2 oc = *reinterpret_cast<const float2*>(pred + ((size_t)img * NN + i) * 6 + 4);
        s = __fmul_rn(oc.x, oc.y);
        g_scores[(size_t)img * NN + i] = s;
    }
    __shared__ float red[32];
    #pragma unroll
    for (int o = 16; o; o >>= 1) s = fmaxf(s, __shfl_xor_sync(0xffffffffu, s, o));
    if ((threadIdx.x & 31) == 0) red[threadIdx.x >> 5] = s;
    __syncthreads();
    if (threadIdx.x < 32) {
        float v = red[threadIdx.x];
        #pragma unroll
        for (int o = 16; o; o >>= 1) v = fmaxf(v, __shfl_xor_sync(0xffffffffu, v, o));
        if (threadIdx.x == 0) atomicMax(&g_maxbits[img], __float_as_uint(v));
    }
}

// ---------------- K2: masked histogram (grid-wide, global atomics) ----------------
__global__ void __launch_bounds__(1024) k_hist() {
    const int img = blockIdx.y;
    __shared__ float sThr;
    if (threadIdx.x == 0) sThr = calc_thr(__uint_as_float(g_maxbits[img]));
    __syncthreads();
    const float thr = sThr;
    int i = blockIdx.x * 1024 + threadIdx.x;
    if (i < NN) {
        float s = g_scores[(size_t)img * NN + i];
        float m = (s >= thr) ? s : 0.f;
        unsigned b = __float_as_uint(m) >> 16;
        if (b != 0u) atomicAdd(&g_hist[img * HBUCK + b], 1u);
    }
}

// ---------------- K3: boundary bucket per image ----------------
__global__ void __launch_bounds__(1024) k_bounds() {
    __shared__ unsigned upart[1024];
    __shared__ int sTstar;
    const int img = blockIdx.x, tid = threadIdx.x;
    const unsigned* hist = &g_hist[img * HBUCK];
    if (tid == 0) sTstar = 0;
    unsigned p = 0;
    #pragma unroll
    for (int b = 0; b < 16; ++b) p += hist[tid * 16 + b];
    upart[tid] = p;
    __syncthreads();
    for (int off = 1; off < 1024; off <<= 1) {
        unsigned v = (tid + off < 1024) ? upart[tid + off] : 0u;
        __syncthreads();
        upart[tid] += v;
        __syncthreads();
    }
    if (upart[tid] >= KK && (tid == 1023 || upart[tid + 1] < KK)) sTstar = tid;
    __syncthreads();
    if (tid == 0) {
        unsigned bst;
        if (upart[0] < KK) {
            bst = 1u;                                  // <512 positives: take all
        } else {
            int t = sTstar;
            unsigned c = (t < 1023) ? upart[t + 1] : 0u;
            bst = 1u;
            for (int b = t * 16 + 15; b >= t * 16; --b) {
                if (b <= 0) { bst = 1u; break; }
                c += hist[b];
                if (c >= KK) { bst = (unsigned)b; break; }
            }
            if (bst == 0u) bst = 1u;
        }
        g_bstar[img] = bst;
    }
}

// ---------------- K4: gather candidate keys (grid-wide) ----------------
__global__ void __launch_bounds__(1024) k_gather() {
    const int img = blockIdx.y;
    __shared__ float sThr;
    __shared__ unsigned sB;
    if (threadIdx.x == 0) {
        sThr = calc_thr(__uint_as_float(g_maxbits[img]));
        sB = g_bstar[img];
    }
    __syncthreads();
    const float thr = sThr;
    const unsigned bstar = sB;
    int i = blockIdx.x * 1024 + threadIdx.x;
    if (i < NN) {
        float s = g_scores[(size_t)img * NN + i];
        float m = (s >= thr) ? s : 0.f;
        unsigned bits = __float_as_uint(m);
        if ((bits >> 16) >= bstar) {
            int pz = atomicAdd(&g_cnt[img], 1);
            if (pz < CAP)
                g_keys[img * CAP + pz] = ((unsigned long long)bits << 32) |
                                         (unsigned long long)(0xFFFFFFFFu - (unsigned)i);
        }
    }
}

// ---------------- K5: bitonic sort (warp-shfl inner phases) + materialize ----------------
__global__ void __launch_bounds__(1024) k_sort(const float* __restrict__ pred) {
    __shared__ unsigned long long buf[CAP];
    const int img = blockIdx.x, tid = threadIdx.x;
    int cnt = g_cnt[img]; if (cnt > CAP) cnt = CAP;
    int S = 1024;
    while (S < cnt) S <<= 1;                      // S in {1024,2048,4096}
    for (int i = tid; i < S; i += 1024)
        buf[i] = (i < cnt) ? g_keys[img * CAP + i] : 0ull;
    __syncthreads();

    const int R = S >> 10;
    for (int k = 2; k <= S; k <<= 1) {
        // smem phases: j >= 32
        for (int j = k >> 1; j >= 32; j >>= 1) {
            for (int i = tid; i < S; i += 1024) {
                int l = i ^ j;
                if (l > i) {
                    unsigned long long a = buf[i], b = buf[l];
                    bool up = ((i & k) == 0);
                    if ((a < b) == up) { buf[i] = b; buf[l] = a; }
                }
            }
            __syncthreads();
        }
        // register phases: j <= 16, within-warp shfl
        int j0 = ((k >> 1) < 32) ? (k >> 1) : 16;
        for (int r = 0; r < R; ++r) {
            int i = tid + (r << 10);
            unsigned long long v = buf[i];
            bool up = ((i & k) == 0);
            for (int j = j0; j >= 1; j >>= 1) {
                unsigned long long o = __shfl_xor_sync(0xffffffffu, v, j);
                bool takemax = (up == ((i & j) == 0));
                v = takemax ? (v > o ? v : o) : (v < o ? v : o);
            }
            buf[i] = v;
        }
        __syncthreads();
    }

    // materialize 512 candidates
    if (tid < KK) {
        unsigned long long key = buf[tid];
        unsigned bits = (unsigned)(key >> 32);
        unsigned idx  = 0xFFFFFFFFu - (unsigned)(key & 0xFFFFFFFFull);
        float x1 = 0.f, y1 = 0.f, x2 = 0.f, y2 = 0.f, ar = 0.f, ob = 0.f, cf = 0.f, vd = 0.f;
        if (bits != 0u && idx < (unsigned)NN) {
            const float* row = pred + ((size_t)img * NN + idx) * 6;
            float cx = row[0], cy = row[1], w = row[2], h = row[3];
            ob = row[4]; cf = row[5];
            float hw = __fmul_rn(w, 0.5f), hh = __fmul_rn(h, 0.5f);
            x1 = __fsub_rn(cx, hw); y1 = __fsub_rn(cy, hh);
            x2 = __fadd_rn(cx, hw); y2 = __fadd_rn(cy, hh);
            ar = __fmul_rn(fmaxf(__fsub_rn(x2, x1), 0.f),
                           fmaxf(__fsub_rn(y2, y1), 0.f));
            vd = 1.f;
        }
        float* cd = g_cand[img][tid];
        cd[0] = x1; cd[1] = y1; cd[2] = x2; cd[3] = y2;
        cd[4] = ar; cd[5] = ob; cd[6] = cf; cd[7] = vd;
    }
}

// ---------------- K6: suppressor matrix, transposed layout (grid-wide) ----------------
__global__ void __launch_bounds__(256) k_supc() {
    __shared__ float bx1[KK], by1[KK], bx2[KK], by2[KK], bar[KK];
    const int img = blockIdx.y, chunk = blockIdx.x, tid = threadIdx.x;
    for (int c = tid; c < KK; c += 256) {
        const float* cd = g_cand[img][c];
        bx1[c] = cd[0]; by1[c] = cd[1]; bx2[c] = cd[2]; by2[c] = cd[3]; bar[c] = cd[4];
    }
    __syncthreads();
    #pragma unroll
    for (int s = 0; s < 4; ++s) {
        int t = tid + s * 256;                // (row-in-chunk, word)
        int i = chunk * 64 + (t >> 4);
        int w = t & 15;
        unsigned bits = 0u;
        int jb = w << 5;
        if (jb < i) {
            float x1 = bx1[i], yy1 = by1[i], x2 = bx2[i], yy2 = by2[i], ai = bar[i];
            int lmax = i - jb; if (lmax > 32) lmax = 32;
            for (int l = 0; l < lmax; ++l) {
                int j = jb + l;
                float ltx = fmaxf(x1,  bx1[j]);
                float lty = fmaxf(yy1, by1[j]);
                float rbx = fminf(x2,  bx2[j]);
                float rby = fminf(yy2, by2[j]);
                float wd = fmaxf(__fsub_rn(rbx, ltx), 0.f);
                float hg = fmaxf(__fsub_rn(rby, lty), 0.f);
                float inter = __fmul_rn(wd, hg);
                float den = __fadd_rn(__fsub_rn(__fadd_rn(ai, bar[j]), inter), 1e-9f);
                float iou = __fdiv_rn(inter, den);
                if (iou > IOU_T) bits |= (1u << l);
            }
        }
        g_supc[img][w][i] = bits;             // transposed store
    }
}

// ---------------- K7: fixpoint NMS + output ----------------
__global__ void __launch_bounds__(512) k_nms(float* __restrict__ out) {
    __shared__ __align__(16) unsigned supc[16 * KK];   // [word][box] — conflict-free reads
    __shared__ unsigned s_keep[16], s_new[16];
    __shared__ int s_pfx[16], s_slot[MAXD], sChanged;
    const int img = blockIdx.x, tid = threadIdx.x;

    const uint4* src = reinterpret_cast<const uint4*>(&g_supc[img][0][0]);
    uint4* dst = reinterpret_cast<uint4*>(supc);
    for (int i = tid; i < (16 * KK) / 4; i += 512) dst[i] = src[i];
    int vbit = (g_cand[img][tid][7] != 0.f);
    unsigned wb = __ballot_sync(0xffffffffu, vbit);
    if ((tid & 31) == 0) s_keep[tid >> 5] = wb;
    __syncthreads();

    for (int r = 0; r < KK; ++r) {
        if (tid == 0) sChanged = 0;
        __syncthreads();
        unsigned sup = 0u;
        #pragma unroll
        for (int w = 0; w < 16; ++w) sup |= s_keep[w] & supc[w * KK + tid];
        int bit = vbit && (sup == 0u);
        unsigned nb = __ballot_sync(0xffffffffu, bit);
        if ((tid & 31) == 0) {
            s_new[tid >> 5] = nb;
            if (nb != s_keep[tid >> 5]) sChanged = 1;
        }
        __syncthreads();
        if (tid < 16) s_keep[tid] = s_new[tid];
        __syncthreads();
        if (!sChanged) break;
    }

    if (tid == 0) {
        int acc = 0;
        for (int w = 0; w < 16; ++w) { s_pfx[w] = acc; acc += __popc(s_keep[w]); }
    }
    if (tid < MAXD) s_slot[tid] = -1;
    __syncthreads();
    {
        int w = tid >> 5, b = tid & 31;
        if ((s_keep[w] >> b) & 1u) {
            int rk = s_pfx[w] + __popc(s_keep[w] & ((1u << b) - 1u));
            if (rk < MAXD) s_slot[rk] = tid;
        }
    }
    __syncthreads();
    if (tid < MAXD) {
        int c = s_slot[tid];
        float r0 = 0.f, r1 = 0.f, r2 = 0.f, r3 = 0.f, r4 = 0.f, r5 = 0.f, mk = 0.f;
        if (c >= 0) {
            const float* cd = g_cand[img][c];
            r0 = cd[0]; r1 = cd[1]; r2 = cd[2]; r3 = cd[3];
            r4 = cd[5]; r5 = cd[6]; mk = 1.f;
        }
        float* o = out + (size_t)img * (MAXD * 7) + (size_t)tid * 7;
        o[0] = r0; o[1] = r1; o[2] = r2; o[3] = r3; o[4] = r4; o[5] = r5; o[6] = 0.f;
        out[MASK_OFF + img * MAXD + tid] = mk;
    }
}

// ---------------- launcher ----------------
extern "C" void kernel_launch(void* const* d_in, const int* in_sizes, int n_in,
                              void* d_out, int out_size) {
    const float* pred = (const float*)d_in[0];
    const float* feat = (const float*)d_in[1];
    float* out = (float*)d_out;

    static cudaStream_t s2 = nullptr;
    static cudaEvent_t evA = nullptr, evB = nullptr;
    static void* histAddr = nullptr;
    static void* cntAddr = nullptr;
    if (!s2) {
        cudaStreamCreateWithFlags(&s2, cudaStreamNonBlocking);
        cudaEventCreateWithFlags(&evA, cudaEventDisableTiming);
        cudaEventCreateWithFlags(&evB, cudaEventDisableTiming);
        cudaGetSymbolAddress(&histAddr, g_hist);
        cudaGetSymbolAddress(&cntAddr, g_cnt);
    }

    // fork: big features copy runs concurrently with the detection pipeline
    cudaEventRecord(evA, 0);
    cudaStreamWaitEvent(s2, evA, 0);
    cudaMemcpyAsync(out + FEAT_OFF, feat, (size_t)FEAT_N * sizeof(float),
                    cudaMemcpyDeviceToDevice, s2);
    cudaEventRecord(evB, s2);

    // scratch resets (graph memset nodes, replayed each launch)
    cudaMemsetAsync(histAddr, 0, (size_t)BB * HBUCK * sizeof(unsigned), 0);
    cudaMemsetAsync(cntAddr, 0, (size_t)BB * sizeof(int), 0);

    k_scores<<<dim3(48, BB), 1024>>>(pred);
    k_hist  <<<dim3(48, BB), 1024>>>();
    k_bounds<<<BB, 1024>>>();
    k_gather<<<dim3(48, BB), 1024>>>();
    k_sort  <<<BB, 1024>>>(pred);
    k_supc  <<<dim3(8, BB), 256>>>();
    k_nms   <<<BB, 512>>>(out);

    cudaStreamWaitEvent(0, evB, 0);
}